// round 8
// baseline (speedup 1.0000x reference)
#include <cuda_runtime.h>
#include <math.h>

// Problem constants (fixed by the reference)
#define HH 512
#define WW 512
#define HP 64
#define WP 2048
#define BB 4
#define CC 64
#define HW (HH * WW)          // 262144 cart pixels per plane
#define PLANE (HP * WP)       // 131072 polar elements per plane

// Block = 256 threads covering a 32(x) x 8(y) cart tile for one b.
// Warp lanes form an 8x4 patch (narrow polar footprint per gather LDG).
// Stores are re-coalesced through a double-buffered smem tile
// (8 channels x 8 rows x 32 cols, row stride 40, 16B-aligned rows),
// one barrier per 8-channel group, float4 store phase.
__global__ void __launch_bounds__(256, 8)
k_fused(const float* __restrict__ polar,
        const float* __restrict__ ref,
        float*       __restrict__ out) {
    __shared__ float sbuf[2][8 * 8 * 40];

    const int tid  = threadIdx.x;
    const int warp = tid >> 5;
    const int lane = tid & 31;

    // warp tile: 4 warps across x (8 px each), 2 down y (4 rows each)
    const int tx = ((warp & 3) << 3) | (lane & 7);   // 0..31
    const int ty = ((warp >> 2) << 2) | (lane >> 3); // 0..7

    const int bx = blockIdx.x;
    const int by = blockIdx.y;
    const int b  = blockIdx.z;

    const int x = (bx << 5) + tx;
    const int y = (by << 3) + ty;

    // ---- analytic map (mask chain bitwise == numpy) ----
    const float c1  = 362.03867196751236f;           // f32(256*sqrt(2))
    const float PIf = 3.14159265358979323846f;       // f32(np.pi)

    const float yyc = ((float)y - 256.0f) + 0.5f;
    const float xxc = ((float)x - 256.0f) + 0.5f;

    float d2    = __fadd_rn(__fmul_rn(xxc, xxc), __fmul_rn(yyc, yyc));
    float depth = __fsqrt_rn(d2);
    float index_y = __fsub_rn(__fmul_rn(__fdiv_rn(depth, c1), 67.0f), 3.0f);
    const bool mapped = (index_y > 0.0f);

    float phi     = PIf - atan2f(yyc, xxc);
    float index_x = phi / PIf / 2.0f * (float)WP;
    float gx  = index_x / (float)WP * 2.0f - 1.0f;
    float gyv = -(index_y / (float)HP * 2.0f - 1.0f);
    float ixf = (gx  + 1.0f) * ((WP - 1) * 0.5f);
    float iyf = (gyv + 1.0f) * ((HP - 1) * 0.5f);

    float x0f = floorf(ixf);
    float y0f = floorf(iyf);
    float wx  = ixf - x0f;
    float wy  = iyf - y0f;
    int   x0  = (int)x0f;
    int   y0  = (int)y0f;

    y0 = min(max(y0, 0), HP - 2);
    if (x0 < 0)      { x0 = 0;      wx = 0.0f; }
    if (x0 > WP - 2) { x0 = WP - 2; wx = 1.0f; }

    float wxm = 1.0f - wx, wym = 1.0f - wy;
    const float w00 = wxm * wym;
    const float w01 = wx  * wym;
    const float w10 = wxm * wy;
    const float w11 = wx  * wy;
    const int   pk  = y0 * WP + x0;

    const float* pbase = polar + (size_t)b * CC * PLANE + pk;
    const float* rbase = ref + ((size_t)b * CC) * HW + (size_t)y * WW + x;
    const size_t obase_blk = ((size_t)b * CC) * HW
                           + (size_t)(by << 3) * WW + (bx << 5);
    const int sidx = ty * 40 + tx;   // conflict-free for 8x4 patches

    // store-phase decomposition (float4 granularity):
    // 512 float4 per group, 2 per thread
    const int s_xx4 = tid & 7;          // float4 column (0..7)
    const int s_yy  = (tid >> 3) & 7;   // row (0..7)
    const int s_g0  = tid >> 6;         // channel-in-group 0..3 (i=0) / +4 (i=1)

    // ---- gather one 8-channel group into sbuf[buf] ----
    auto stage = [&](int cg, int buf) {
        if (mapped) {
            const float* pp = pbase + (size_t)(cg << 3) * PLANE;
            #pragma unroll
            for (int g = 0; g < 8; ++g) {
                float v00 = __ldg(pp);
                float v01 = __ldg(pp + 1);
                float v10 = __ldg(pp + WP);
                float v11 = __ldg(pp + WP + 1);
                sbuf[buf][g * (8 * 40) + sidx] =
                    v00 * w00 + v01 * w01 + v10 * w10 + v11 * w11;
                pp += PLANE;
            }
        } else {
            const float* r = rbase + (size_t)(cg << 3) * HW;
            #pragma unroll
            for (int g = 0; g < 8; ++g) {
                sbuf[buf][g * (8 * 40) + sidx] = __ldg(r);
                r += HW;
            }
        }
    };

    // ---- write one 8-channel group out (float4, fully coalesced) ----
    auto flush = [&](int cg, int buf) {
        #pragma unroll
        for (int i = 0; i < 2; ++i) {
            int g  = s_g0 + i * 4;
            const float4 v = *(const float4*)&sbuf[buf][(g * 8 + s_yy) * 40
                                                        + s_xx4 * 4];
            __stcs((float4*)(out + obase_blk
                             + (size_t)((cg << 3) + g) * HW
                             + (size_t)s_yy * WW + s_xx4 * 4),
                   v);
        }
    };

    stage(0, 0);
    __syncthreads();
    #pragma unroll
    for (int cg = 0; cg < 7; ++cg) {
        stage(cg + 1, (cg + 1) & 1);   // long-latency LDGs issued first
        flush(cg, cg & 1);             // overlaps with in-flight gathers
        __syncthreads();
    }
    flush(7, 1);
}

extern "C" void kernel_launch(void* const* d_in, const int* in_sizes, int n_in,
                              void* d_out, int out_size) {
    const float* polar = (const float*)d_in[0];   // [B,C,HP,WP]
    const float* ref   = (const float*)d_in[1];   // [B,C,H,W]
    float*       out   = (float*)d_out;           // [B,C,H,W]

    dim3 grid(WW / 32, HH / 8, BB);   // (16, 64, 4) = 4096 blocks
    k_fused<<<grid, 256>>>(polar, ref, out);
}